// round 10
// baseline (speedup 1.0000x reference)
#include <cuda_runtime.h>

#define NUM_CLASSES 23
#define HW (512*512)               // 262144 = 2^18
#define HW_SHIFT 18
#define NPIX (8*HW)                // 2097152
#define GRID 444                   // 148 SMs x 3 blocks = one exact wave
#define BLOCK 256
#define NWARPS (BLOCK/32)
#define NVALS (2*NUM_CLASSES + 1)  // 47
#define SMOOTH 1e-5f
#define CNT_SHIFT 43
#define FIX_SCALE 16777216.0f      // 2^24
#define INV_FIX   (1.0f/16777216.0f)

__device__ float g_scratch[NVALS * GRID];
__device__ unsigned int g_count;   // zero-init; self-resetting each launch

__device__ __forceinline__ float warp_sum(float v) {
    #pragma unroll
    for (int off = 16; off; off >>= 1)
        v += __shfl_down_sync(0xffffffffu, v, off);
    return v;
}

__global__ __launch_bounds__(BLOCK, 3)
void combined_loss_fused(const float* __restrict__ pred,
                         const int*  __restrict__ tgt,
                         float* __restrict__ out)
{
    // Per-warp packed accumulators: bits[43:64)=count, bits[0:43)=inter*2^24
    __shared__ unsigned long long s_ic[NWARPS][NUM_CLASSES];
    for (int i = threadIdx.x; i < NWARPS * NUM_CLASSES; i += BLOCK)
        ((unsigned long long*)s_ic)[i] = 0ull;
    __syncthreads();

    float acc_den[NUM_CLASSES];
    #pragma unroll
    for (int c = 0; c < NUM_CLASSES; c++) acc_den[c] = 0.f;
    float acc_ce = 0.f;

    const int lane = threadIdx.x & 31;
    const int warp = threadIdx.x >> 5;
    const int tid0   = blockIdx.x * BLOCK + threadIdx.x;
    const int stride = GRID * BLOCK;

    for (int p = tid0; p < NPIX; p += stride) {
        const int b  = p >> HW_SHIFT;
        const int hw = p & (HW - 1);
        const float* base = pred + (size_t)b * (NUM_CLASSES * HW) + hw;
        const int t = tgt[p];

        // One pixel/thread: x[23] keeps the live set ~65 regs -> 24 warps/SM.
        // FMAX chain = scheduling barrier: all 23 LDG.32 batched (MLP~23).
        float x[NUM_CLASSES];
        float m = -1e30f;
        float xt = 0.f;
        #pragma unroll
        for (int c = 0; c < NUM_CLASSES; c++) {
            x[c] = base[c * HW];
            m = fmaxf(m, x[c]);
            xt = (c == t) ? x[c] : xt;
        }

        // exp in place + sum
        float s = 0.f;
        #pragma unroll
        for (int c = 0; c < NUM_CLASSES; c++) {
            x[c] = __expf(x[c] - m);
            s += x[c];
        }
        const float inv = 1.0f / s;

        // denominator accumulation (1 FFMA/class)
        #pragma unroll
        for (int c = 0; c < NUM_CLASSES; c++)
            acc_den[c] = fmaf(x[c], inv, acc_den[c]);

        // CE + p_t
        acc_ce += (m + __logf(s)) - xt;
        const float pt = __expf(xt - m) * inv;

        const unsigned long long u =
            (unsigned long long)(pt * FIX_SCALE) + (1ull << CNT_SHIFT);
        atomicAdd(&s_ic[warp][t], u);
    }

    // Deterministic block reduction for den + ce
    __shared__ float s_part[NUM_CLASSES + 1][NWARPS];
    #pragma unroll
    for (int c = 0; c < NUM_CLASSES; c++) {
        float v = warp_sum(acc_den[c]);
        if (lane == 0) s_part[c][warp] = v;
    }
    {
        float v = warp_sum(acc_ce);
        if (lane == 0) s_part[NUM_CLASSES][warp] = v;
    }
    __syncthreads();

    if (threadIdx.x < NUM_CLASSES) {
        const int c = threadIdx.x;
        unsigned long long tot = 0ull;
        float den = 0.f;
        #pragma unroll
        for (int w = 0; w < NWARPS; w++) {
            tot += s_ic[w][c];
            den += s_part[c][w];
        }
        const float inter = (float)(tot & ((1ull << CNT_SHIFT) - 1ull)) * INV_FIX;
        const float cnt   = (float)(tot >> CNT_SHIFT);
        g_scratch[c * GRID + blockIdx.x] = inter;
        g_scratch[(NUM_CLASSES + c) * GRID + blockIdx.x] = den + cnt;
    } else if (threadIdx.x == NUM_CLASSES) {
        float ce = 0.f;
        #pragma unroll
        for (int w = 0; w < NWARPS; w++) ce += s_part[NUM_CLASSES][w];
        g_scratch[2 * NUM_CLASSES * GRID + blockIdx.x] = ce;
    }

    // Last-block final reduction (fixed block-index order -> deterministic)
    __shared__ bool is_last;
    __threadfence();
    if (threadIdx.x == 0) {
        unsigned int v = atomicAdd(&g_count, 1u);
        is_last = (v == GRID - 1);
        if (is_last) g_count = 0u;   // reset for next graph replay
    }
    __syncthreads();
    if (!is_last) return;

    __shared__ float finals[NVALS];
    for (int v = warp; v < NVALS; v += NWARPS) {
        float s = 0.f;
        for (int bk = lane; bk < GRID; bk += 32)
            s += __ldcg(&g_scratch[v * GRID + bk]);
        s = warp_sum(s);
        if (lane == 0) finals[v] = s;
    }
    __syncthreads();

    if (threadIdx.x == 0) {
        float dl = 0.f;
        #pragma unroll
        for (int c = 0; c < NUM_CLASSES; c++) {
            const float inter = finals[c];
            const float den   = finals[NUM_CLASSES + c];
            dl += 1.0f - (2.0f * inter + SMOOTH) / (den + SMOOTH);
        }
        dl *= (1.0f / NUM_CLASSES);
        const float ce = finals[2 * NUM_CLASSES] * (1.0f / (float)NPIX);
        out[0] = 0.5f * dl + 0.5f * ce;
    }
}

extern "C" void kernel_launch(void* const* d_in, const int* in_sizes, int n_in,
                              void* d_out, int out_size)
{
    const float* pred = (const float*)d_in[0];
    const int*   tgt  = (const int*)d_in[1];
    float*       out  = (float*)d_out;
    (void)in_sizes; (void)n_in; (void)out_size;

    combined_loss_fused<<<GRID, BLOCK>>>(pred, tgt, out);
}

// round 11
// speedup vs baseline: 1.1348x; 1.1348x over previous
#include <cuda_runtime.h>

#define NUM_CLASSES 23
#define HW (512*512)               // 262144 = 2^18
#define HW_SHIFT 18
#define NPIX (8*HW)                // 2097152
#define GRID 592                   // 148 SMs x 4 blocks = one exact wave
#define BLOCK 256
#define NWARPS (BLOCK/32)
#define NVALS (2*NUM_CLASSES + 1)  // 47
#define SMOOTH 1e-5f
#define CNT_SHIFT 43
#define FIX_SCALE 16777216.0f      // 2^24
#define INV_FIX   (1.0f/16777216.0f)

__device__ float g_scratch[NVALS * GRID];
__device__ unsigned int g_count;   // zero-init; self-resetting each launch

__device__ __forceinline__ float warp_sum(float v) {
    #pragma unroll
    for (int off = 16; off; off >>= 1)
        v += __shfl_down_sync(0xffffffffu, v, off);
    return v;
}

// Paired reduction: even offsets only, so even-lane and odd-lane values
// (different class sets) never mix. lane0 = sum over even lanes,
// lane1 = sum over odd lanes.
__device__ __forceinline__ float warp_sum_pair(float v) {
    #pragma unroll
    for (int off = 16; off >= 2; off >>= 1)
        v += __shfl_down_sync(0xffffffffu, v, off);
    return v;
}

__global__ __launch_bounds__(BLOCK, 4)
void combined_loss_fused(const float* __restrict__ pred,
                         const int*  __restrict__ tgt,
                         float* __restrict__ out)
{
    // Per-warp packed accumulators: bits[43:64)=count, bits[0:43)=inter*2^24
    __shared__ unsigned long long s_ic[NWARPS][NUM_CLASSES];
    for (int i = threadIdx.x; i < NWARPS * NUM_CLASSES; i += BLOCK)
        ((unsigned long long*)s_ic)[i] = 0ull;
    __syncthreads();

    // Each lane owns 12 class slots: even lane -> classes 0..11,
    // odd lane -> classes 12..22 (slot 11 of odd lanes stays zero).
    float acc_den[12];
    #pragma unroll
    for (int i = 0; i < 12; i++) acc_den[i] = 0.f;
    float acc_ce = 0.f;

    const int lane  = threadIdx.x & 31;
    const int warp  = threadIdx.x >> 5;
    const int half  = threadIdx.x & 1;    // 0: classes 0-11, 1: classes 12-22
    const int cbase = half * 12;

    const int gt      = blockIdx.x * BLOCK + threadIdx.x;
    const int pix0    = gt >> 1;
    const int pstride = (GRID * BLOCK) >> 1;

    for (int p = pix0; p < NPIX; p += pstride) {
        const int b  = p >> HW_SHIFT;
        const int hw = p & (HW - 1);
        const float* base = pred + (size_t)b * (NUM_CLASSES * HW) + hw;
        const int t = tgt[p];

        // Load own 11 classes unconditionally (cbase+i <= 22 for i<11);
        // class 11 only exists for the even half.
        float x[11];
        float m  = -1e30f;
        float xt = 0.f;
        #pragma unroll
        for (int i = 0; i < 11; i++) {
            x[i] = base[(cbase + i) * HW];
            m = fmaxf(m, x[i]);
            xt = (cbase + i == t) ? x[i] : xt;
        }
        float x11 = -1e30f;                 // exp(-1e30 - m) flushes to 0
        if (half == 0) {
            x11 = base[11 * HW];
            xt  = (t == 11) ? x11 : xt;
        }
        m = fmaxf(m, x11);

        // Combine across the lane pair: max, then (after exp) sum and x_t.
        m = fmaxf(m, __shfl_xor_sync(0xffffffffu, m, 1));

        float s = 0.f;
        #pragma unroll
        for (int i = 0; i < 11; i++) {
            x[i] = __expf(x[i] - m);
            s += x[i];
        }
        x11 = __expf(x11 - m);              // 0 for the odd half
        s += x11;

        s  += __shfl_xor_sync(0xffffffffu, s, 1);
        xt += __shfl_xor_sync(0xffffffffu, xt, 1);   // non-owner holds 0
        const float inv = 1.0f / s;

        // Per-class denominator (own classes only)
        #pragma unroll
        for (int i = 0; i < 11; i++)
            acc_den[i] = fmaf(x[i], inv, acc_den[i]);
        acc_den[11] = fmaf(x11, inv, acc_den[11]);

        // CE + inter/count: even lane only (one contribution per pixel)
        if (half == 0) {
            acc_ce += (m + __logf(s)) - xt;
            const float pt = __expf(xt - m) * inv;
            const unsigned long long u =
                (unsigned long long)(pt * FIX_SCALE) + (1ull << CNT_SHIFT);
            atomicAdd(&s_ic[warp][t], u);
        }
    }

    // Deterministic block reduction for den + ce
    __shared__ float s_part[NUM_CLASSES + 1][NWARPS];
    #pragma unroll
    for (int i = 0; i < 12; i++) {
        float v = warp_sum_pair(acc_den[i]);
        if (lane == 0) s_part[i][warp] = v;                 // class i
        if (lane == 1 && i < 11) s_part[12 + i][warp] = v;  // class 12+i
    }
    {
        float v = warp_sum(acc_ce);       // odd lanes hold 0
        if (lane == 0) s_part[NUM_CLASSES][warp] = v;
    }
    __syncthreads();

    if (threadIdx.x < NUM_CLASSES) {
        const int c = threadIdx.x;
        unsigned long long tot = 0ull;
        float den = 0.f;
        #pragma unroll
        for (int w = 0; w < NWARPS; w++) {
            tot += s_ic[w][c];
            den += s_part[c][w];
        }
        const float inter = (float)(tot & ((1ull << CNT_SHIFT) - 1ull)) * INV_FIX;
        const float cnt   = (float)(tot >> CNT_SHIFT);
        g_scratch[c * GRID + blockIdx.x] = inter;
        g_scratch[(NUM_CLASSES + c) * GRID + blockIdx.x] = den + cnt;
    } else if (threadIdx.x == NUM_CLASSES) {
        float ce = 0.f;
        #pragma unroll
        for (int w = 0; w < NWARPS; w++) ce += s_part[NUM_CLASSES][w];
        g_scratch[2 * NUM_CLASSES * GRID + blockIdx.x] = ce;
    }

    // Last-block final reduction (fixed block-index order -> deterministic)
    __shared__ bool is_last;
    __threadfence();
    if (threadIdx.x == 0) {
        unsigned int v = atomicAdd(&g_count, 1u);
        is_last = (v == GRID - 1);
        if (is_last) g_count = 0u;   // reset for next graph replay
    }
    __syncthreads();
    if (!is_last) return;

    __shared__ float finals[NVALS];
    for (int v = warp; v < NVALS; v += NWARPS) {
        float s = 0.f;
        for (int bk = lane; bk < GRID; bk += 32)
            s += __ldcg(&g_scratch[v * GRID + bk]);
        s = warp_sum(s);
        if (lane == 0) finals[v] = s;
    }
    __syncthreads();

    if (threadIdx.x == 0) {
        float dl = 0.f;
        #pragma unroll
        for (int c = 0; c < NUM_CLASSES; c++) {
            const float inter = finals[c];
            const float den   = finals[NUM_CLASSES + c];
            dl += 1.0f - (2.0f * inter + SMOOTH) / (den + SMOOTH);
        }
        dl *= (1.0f / NUM_CLASSES);
        const float ce = finals[2 * NUM_CLASSES] * (1.0f / (float)NPIX);
        out[0] = 0.5f * dl + 0.5f * ce;
    }
}

extern "C" void kernel_launch(void* const* d_in, const int* in_sizes, int n_in,
                              void* d_out, int out_size)
{
    const float* pred = (const float*)d_in[0];
    const int*   tgt  = (const int*)d_in[1];
    float*       out  = (float*)d_out;
    (void)in_sizes; (void)n_in; (void)out_size;

    combined_loss_fused<<<GRID, BLOCK>>>(pred, tgt, out);
}

// round 12
// speedup vs baseline: 1.1365x; 1.0015x over previous
#include <cuda_runtime.h>

#define NUM_CLASSES 23
#define HW (512*512)               // 262144 = 2^18
#define HW_SHIFT 18
#define NPIX (8*HW)                // 2097152
#define NPAIR (NPIX/2)             // 1048576 pixel pairs
#define GRID 444                   // 148 SMs x 3 blocks = one exact wave
#define BLOCK 256
#define NWARPS (BLOCK/32)
#define NVALS (2*NUM_CLASSES + 1)  // 47
#define SMOOTH 1e-5f
#define CNT_SHIFT 43
#define FIX_SCALE 16777216.0f      // 2^24
#define INV_FIX   (1.0f/16777216.0f)

__device__ float g_scratch[NVALS * GRID];
__device__ unsigned int g_count;   // zero-init; self-resetting each launch

__device__ __forceinline__ float warp_sum(float v) {
    #pragma unroll
    for (int off = 16; off; off >>= 1)
        v += __shfl_down_sync(0xffffffffu, v, off);
    return v;
}

// Even-offset-only reduction: even-lane and odd-lane values (different class
// sets) never mix. lane0 = sum over even lanes, lane1 = sum over odd lanes.
__device__ __forceinline__ float warp_sum_pair(float v) {
    #pragma unroll
    for (int off = 16; off >= 2; off >>= 1)
        v += __shfl_down_sync(0xffffffffu, v, off);
    return v;
}

__global__ __launch_bounds__(BLOCK, 3)
void combined_loss_fused(const float* __restrict__ pred,
                         const int*  __restrict__ tgt,
                         float* __restrict__ out)
{
    // Per-warp packed accumulators: bits[43:64)=count, bits[0:43)=inter*2^24
    __shared__ unsigned long long s_ic[NWARPS][NUM_CLASSES];
    for (int i = threadIdx.x; i < NWARPS * NUM_CLASSES; i += BLOCK)
        ((unsigned long long*)s_ic)[i] = 0ull;
    __syncthreads();

    // Lane pair: even lane owns classes 0..11, odd lane 12..22 (slot 11 dead).
    float acc_den[12];
    #pragma unroll
    for (int i = 0; i < 12; i++) acc_den[i] = 0.f;
    float acc_ce = 0.f;

    const int lane  = threadIdx.x & 31;
    const int warp  = threadIdx.x >> 5;
    const int half  = threadIdx.x & 1;
    const int cbase = half * 12;

    const int gt      = blockIdx.x * BLOCK + threadIdx.x;
    const int q0      = gt >> 1;                 // pixel-pair index
    const int qstride = (GRID * BLOCK) >> 1;

    for (int q = q0; q < NPAIR; q += qstride) {
        const int p  = q << 1;
        const int b  = p >> HW_SHIFT;
        const int hw = p & (HW - 1);
        const float* base = pred + (size_t)b * (NUM_CLASSES * HW) + hw;
        const int2 t2 = ((const int2*)tgt)[q];   // both lanes broadcast-read

        // Own classes as float2 (2 pixels). FMAX chain batches the loads.
        float2 x[12];
        float m0 = -1e30f, m1 = -1e30f;
        float xt0 = 0.f, xt1 = 0.f;
        #pragma unroll
        for (int i = 0; i < 11; i++) {
            x[i] = *(const float2*)(base + (cbase + i) * HW);
            m0 = fmaxf(m0, x[i].x);
            m1 = fmaxf(m1, x[i].y);
            xt0 = (cbase + i == t2.x) ? x[i].x : xt0;
            xt1 = (cbase + i == t2.y) ? x[i].y : xt1;
        }
        if (half == 0) {                          // class 11 exists only here
            x[11] = *(const float2*)(base + 11 * HW);
            xt0 = (t2.x == 11) ? x[11].x : xt0;
            xt1 = (t2.y == 11) ? x[11].y : xt1;
        } else {
            x[11] = make_float2(-1e30f, -1e30f);  // exp flushes to 0
        }
        m0 = fmaxf(m0, x[11].x);
        m1 = fmaxf(m1, x[11].y);

        // Combine max across the lane pair
        m0 = fmaxf(m0, __shfl_xor_sync(0xffffffffu, m0, 1));
        m1 = fmaxf(m1, __shfl_xor_sync(0xffffffffu, m1, 1));

        // exp in place + partial sums
        float s0 = 0.f, s1 = 0.f;
        #pragma unroll
        for (int i = 0; i < 12; i++) {
            x[i].x = __expf(x[i].x - m0);
            x[i].y = __expf(x[i].y - m1);
            s0 += x[i].x;
            s1 += x[i].y;
        }

        // Combine sums and x_t across the pair (non-owner holds 0)
        s0  += __shfl_xor_sync(0xffffffffu, s0, 1);
        s1  += __shfl_xor_sync(0xffffffffu, s1, 1);
        xt0 += __shfl_xor_sync(0xffffffffu, xt0, 1);
        xt1 += __shfl_xor_sync(0xffffffffu, xt1, 1);
        const float inv0 = 1.0f / s0;
        const float inv1 = 1.0f / s1;

        // Per-class denominator (own classes, both pixels)
        #pragma unroll
        for (int i = 0; i < 12; i++)
            acc_den[i] += fmaf(x[i].y, inv1, x[i].x * inv0);

        // CE + inter/count: even lane only (one contribution per pixel)
        if (half == 0) {
            acc_ce += ((m0 + __logf(s0)) - xt0) + ((m1 + __logf(s1)) - xt1);
            const float pt0 = __expf(xt0 - m0) * inv0;
            const float pt1 = __expf(xt1 - m1) * inv1;
            const unsigned long long u0 =
                (unsigned long long)(pt0 * FIX_SCALE) + (1ull << CNT_SHIFT);
            const unsigned long long u1 =
                (unsigned long long)(pt1 * FIX_SCALE) + (1ull << CNT_SHIFT);
            atomicAdd(&s_ic[warp][t2.x], u0);
            atomicAdd(&s_ic[warp][t2.y], u1);
        }
    }

    // Deterministic block reduction for den + ce
    __shared__ float s_part[NUM_CLASSES + 1][NWARPS];
    #pragma unroll
    for (int i = 0; i < 12; i++) {
        float v = warp_sum_pair(acc_den[i]);
        if (lane == 0) s_part[i][warp] = v;                 // class i
        if (lane == 1 && i < 11) s_part[12 + i][warp] = v;  // class 12+i
    }
    {
        float v = warp_sum(acc_ce);       // odd lanes hold 0
        if (lane == 0) s_part[NUM_CLASSES][warp] = v;
    }
    __syncthreads();

    if (threadIdx.x < NUM_CLASSES) {
        const int c = threadIdx.x;
        unsigned long long tot = 0ull;
        float den = 0.f;
        #pragma unroll
        for (int w = 0; w < NWARPS; w++) {
            tot += s_ic[w][c];
            den += s_part[c][w];
        }
        const float inter = (float)(tot & ((1ull << CNT_SHIFT) - 1ull)) * INV_FIX;
        const float cnt   = (float)(tot >> CNT_SHIFT);
        g_scratch[c * GRID + blockIdx.x] = inter;
        g_scratch[(NUM_CLASSES + c) * GRID + blockIdx.x] = den + cnt;
    } else if (threadIdx.x == NUM_CLASSES) {
        float ce = 0.f;
        #pragma unroll
        for (int w = 0; w < NWARPS; w++) ce += s_part[NUM_CLASSES][w];
        g_scratch[2 * NUM_CLASSES * GRID + blockIdx.x] = ce;
    }

    // Last-block final reduction (fixed block-index order -> deterministic)
    __shared__ bool is_last;
    __threadfence();
    if (threadIdx.x == 0) {
        unsigned int v = atomicAdd(&g_count, 1u);
        is_last = (v == GRID - 1);
        if (is_last) g_count = 0u;   // reset for next graph replay
    }
    __syncthreads();
    if (!is_last) return;

    __shared__ float finals[NVALS];
    for (int v = warp; v < NVALS; v += NWARPS) {
        float s = 0.f;
        for (int bk = lane; bk < GRID; bk += 32)
            s += __ldcg(&g_scratch[v * GRID + bk]);
        s = warp_sum(s);
        if (lane == 0) finals[v] = s;
    }
    __syncthreads();

    if (threadIdx.x == 0) {
        float dl = 0.f;
        #pragma unroll
        for (int c = 0; c < NUM_CLASSES; c++) {
            const float inter = finals[c];
            const float den   = finals[NUM_CLASSES + c];
            dl += 1.0f - (2.0f * inter + SMOOTH) / (den + SMOOTH);
        }
        dl *= (1.0f / NUM_CLASSES);
        const float ce = finals[2 * NUM_CLASSES] * (1.0f / (float)NPIX);
        out[0] = 0.5f * dl + 0.5f * ce;
    }
}

extern "C" void kernel_launch(void* const* d_in, const int* in_sizes, int n_in,
                              void* d_out, int out_size)
{
    const float* pred = (const float*)d_in[0];
    const int*   tgt  = (const int*)d_in[1];
    float*       out  = (float*)d_out;
    (void)in_sizes; (void)n_in; (void)out_size;

    combined_loss_fused<<<GRID, BLOCK>>>(pred, tgt, out);
}

// round 13
// speedup vs baseline: 1.3673x; 1.2030x over previous
#include <cuda_runtime.h>
#include <cstdint>

#define NUM_CLASSES 23
#define HW (512*512)               // 262144 = 2^18
#define HW_SHIFT 18
#define NPIX (8*HW)                // 2097152
#define GRID 296
#define BLOCK 256
#define NWARPS (BLOCK/32)
#define NVALS (2*NUM_CLASSES + 1)  // 47
#define SMOOTH 1e-5f
#define TPX 512                    // pixels per stage (never crosses a batch: HW%512==0)
#define NSTAGES (NPIX/TPX)         // 4096
#define CNT_SHIFT 43
#define FIX_SCALE 16777216.0f      // 2^24
#define INV_FIX   (1.0f/16777216.0f)

// Dynamic smem layout (per block):
// [0, 94208): logits, 2 buffers x 23 rows x 512 floats (47104 B each)
// [94208, 98304): targets, 2 buffers x 512 ints (2048 B each)
#define SM_DATA_BUF 47104
#define SM_TGT_OFF  94208
#define SM_TGT_BUF  2048
#define SM_TOTAL    98304

__device__ float g_scratch[NVALS * GRID];
__device__ unsigned int g_count;   // zero-init; self-resetting each launch

__device__ __forceinline__ float warp_sum(float v) {
    #pragma unroll
    for (int off = 16; off; off >>= 1)
        v += __shfl_down_sync(0xffffffffu, v, off);
    return v;
}

__device__ __forceinline__ void cp16(uint32_t dst, const void* src) {
    asm volatile("cp.async.cg.shared.global [%0], [%1], 16;" :: "r"(dst), "l"(src));
}
__device__ __forceinline__ void cp_commit() {
    asm volatile("cp.async.commit_group;" ::: "memory");
}
__device__ __forceinline__ void cp_wait1() {
    asm volatile("cp.async.wait_group 1;" ::: "memory");
}

// Thread split: hi = tid>>7 (0/1), lo = tid&127.
// hi==0 loads even rows 0,2,..,20 plus row 22; hi==1 loads odd rows 1..21
// plus the 512 targets. Each 16B op covers 4 floats; constant strides.
__device__ __forceinline__ void load_stage(int st, int buf, uint32_t smbase,
                                           const float* __restrict__ pred,
                                           const int*  __restrict__ tgt,
                                           int hi, int lo)
{
    const int p0 = st * TPX;
    const int b  = p0 >> HW_SHIFT;
    const int hw = p0 & (HW - 1);
    const float* base = pred + (size_t)b * (NUM_CLASSES * HW) + hw;
    const uint32_t dst0 = smbase + buf * SM_DATA_BUF + hi * 2048 + lo * 16;
    const float* src0 = base + (size_t)hi * HW + lo * 4;
    #pragma unroll
    for (int k = 0; k < 11; k++)                  // rows 2k+hi = 0..21
        cp16(dst0 + k * 4096, src0 + (size_t)(2 * k) * HW);
    if (hi == 0)                                  // row 22
        cp16(dst0 + 11 * 4096, src0 + (size_t)22 * HW);
    else                                          // targets (128 thr x 16B)
        cp16(smbase + SM_TGT_OFF + buf * SM_TGT_BUF + lo * 16,
             tgt + p0 + lo * 4);
}

__global__ __launch_bounds__(BLOCK, 2)
void combined_loss_fused(const float* __restrict__ pred,
                         const int*  __restrict__ tgt,
                         float* __restrict__ out)
{
    extern __shared__ char smem_raw[];
    uint32_t smbase;
    asm("{ .reg .u64 t; cvta.to.shared.u64 t, %1; cvt.u32.u64 %0, t; }"
        : "=r"(smbase) : "l"(smem_raw));

    // Per-warp packed accumulators: bits[43:64)=count, bits[0:43)=inter*2^24
    __shared__ unsigned long long s_ic[NWARPS][NUM_CLASSES];
    for (int i = threadIdx.x; i < NWARPS * NUM_CLASSES; i += BLOCK)
        ((unsigned long long*)s_ic)[i] = 0ull;
    __syncthreads();

    float acc_den[NUM_CLASSES];
    #pragma unroll
    for (int c = 0; c < NUM_CLASSES; c++) acc_den[c] = 0.f;
    float acc_ce = 0.f;

    const int tid  = threadIdx.x;
    const int lane = tid & 31;
    const int warp = tid >> 5;
    const int hi   = tid >> 7;
    const int lo   = tid & 127;
    const int bk   = blockIdx.x;

    // Pipeline prologue: stages bk (buf0) and bk+GRID (buf1)
    load_stage(bk, 0, smbase, pred, tgt, hi, lo);
    cp_commit();
    if (bk + GRID < NSTAGES)
        load_stage(bk + GRID, 1, smbase, pred, tgt, hi, lo);
    cp_commit();

    for (int i = 0; ; i++) {
        const int st = bk + i * GRID;
        if (st >= NSTAGES) break;
        const int buf = i & 1;

        cp_wait1();            // group i complete (groups finish in order)
        __syncthreads();       // cross-thread visibility of the stage

        const float* sd = (const float*)(smem_raw + buf * SM_DATA_BUF);
        const int2 t2 = ((const int2*)(smem_raw + SM_TGT_OFF + buf * SM_TGT_BUF))[tid];

        // R7's proven body, loads from smem (conflict-free LDS.64).
        float2 x[NUM_CLASSES];
        float m0 = -1e30f, m1 = -1e30f;
        float xt0 = 0.f, xt1 = 0.f;
        #pragma unroll
        for (int c = 0; c < NUM_CLASSES; c++) {
            x[c] = *(const float2*)(sd + c * TPX + 2 * tid);
            m0 = fmaxf(m0, x[c].x);
            m1 = fmaxf(m1, x[c].y);
            xt0 = (c == t2.x) ? x[c].x : xt0;
            xt1 = (c == t2.y) ? x[c].y : xt1;
        }

        float s0 = 0.f, s1 = 0.f;
        #pragma unroll
        for (int c = 0; c < NUM_CLASSES; c++) {
            x[c].x = __expf(x[c].x - m0);
            x[c].y = __expf(x[c].y - m1);
            s0 += x[c].x;
            s1 += x[c].y;
        }
        const float inv0 = 1.0f / s0;
        const float inv1 = 1.0f / s1;

        #pragma unroll
        for (int c = 0; c < NUM_CLASSES; c++)
            acc_den[c] += fmaf(x[c].y, inv1, x[c].x * inv0);

        acc_ce += ((m0 + __logf(s0)) - xt0) + ((m1 + __logf(s1)) - xt1);
        const float pt0 = __expf(xt0 - m0) * inv0;
        const float pt1 = __expf(xt1 - m1) * inv1;

        const unsigned long long u0 =
            (unsigned long long)(pt0 * FIX_SCALE) + (1ull << CNT_SHIFT);
        const unsigned long long u1 =
            (unsigned long long)(pt1 * FIX_SCALE) + (1ull << CNT_SHIFT);
        atomicAdd(&s_ic[warp][t2.x], u0);
        atomicAdd(&s_ic[warp][t2.y], u1);

        __syncthreads();       // everyone done reading buf before refill

        const int stn = st + 2 * GRID;
        if (stn < NSTAGES)
            load_stage(stn, buf, smbase, pred, tgt, hi, lo);
        cp_commit();           // commit even when empty: keeps group count uniform
    }

    // Deterministic block reduction for den + ce
    __shared__ float s_part[NUM_CLASSES + 1][NWARPS];
    #pragma unroll
    for (int c = 0; c < NUM_CLASSES; c++) {
        float v = warp_sum(acc_den[c]);
        if (lane == 0) s_part[c][warp] = v;
    }
    {
        float v = warp_sum(acc_ce);
        if (lane == 0) s_part[NUM_CLASSES][warp] = v;
    }
    __syncthreads();

    if (threadIdx.x < NUM_CLASSES) {
        const int c = threadIdx.x;
        unsigned long long tot = 0ull;
        float den = 0.f;
        #pragma unroll
        for (int w = 0; w < NWARPS; w++) {
            tot += s_ic[w][c];
            den += s_part[c][w];
        }
        const float inter = (float)(tot & ((1ull << CNT_SHIFT) - 1ull)) * INV_FIX;
        const float cnt   = (float)(tot >> CNT_SHIFT);
        g_scratch[c * GRID + blockIdx.x] = inter;
        g_scratch[(NUM_CLASSES + c) * GRID + blockIdx.x] = den + cnt;
    } else if (threadIdx.x == NUM_CLASSES) {
        float ce = 0.f;
        #pragma unroll
        for (int w = 0; w < NWARPS; w++) ce += s_part[NUM_CLASSES][w];
        g_scratch[2 * NUM_CLASSES * GRID + blockIdx.x] = ce;
    }

    // Last-block final reduction (fixed block-index order -> deterministic)
    __shared__ bool is_last;
    __threadfence();
    if (threadIdx.x == 0) {
        unsigned int v = atomicAdd(&g_count, 1u);
        is_last = (v == GRID - 1);
        if (is_last) g_count = 0u;   // reset for next graph replay
    }
    __syncthreads();
    if (!is_last) return;

    __shared__ float finals[NVALS];
    for (int v = warp; v < NVALS; v += NWARPS) {
        float s = 0.f;
        for (int bki = lane; bki < GRID; bki += 32)
            s += __ldcg(&g_scratch[v * GRID + bki]);
        s = warp_sum(s);
        if (lane == 0) finals[v] = s;
    }
    __syncthreads();

    if (threadIdx.x == 0) {
        float dl = 0.f;
        #pragma unroll
        for (int c = 0; c < NUM_CLASSES; c++) {
            const float inter = finals[c];
            const float den   = finals[NUM_CLASSES + c];
            dl += 1.0f - (2.0f * inter + SMOOTH) / (den + SMOOTH);
        }
        dl *= (1.0f / NUM_CLASSES);
        const float ce = finals[2 * NUM_CLASSES] * (1.0f / (float)NPIX);
        out[0] = 0.5f * dl + 0.5f * ce;
    }
}

extern "C" void kernel_launch(void* const* d_in, const int* in_sizes, int n_in,
                              void* d_out, int out_size)
{
    const float* pred = (const float*)d_in[0];
    const int*   tgt  = (const int*)d_in[1];
    float*       out  = (float*)d_out;
    (void)in_sizes; (void)n_in; (void)out_size;

    cudaFuncSetAttribute(combined_loss_fused,
                         cudaFuncAttributeMaxDynamicSharedMemorySize, SM_TOTAL);
    combined_loss_fused<<<GRID, BLOCK, SM_TOTAL>>>(pred, tgt, out);
}

// round 14
// speedup vs baseline: 1.3960x; 1.0210x over previous
#include <cuda_runtime.h>
#include <cstdint>

#define NUM_CLASSES 23
#define HW (512*512)               // 262144 = 2^18
#define HW_SHIFT 18
#define NPIX (8*HW)                // 2097152
#define GRID 444                   // 148 SMs x 3 blocks
#define BLOCK 256
#define NWARPS (BLOCK/32)
#define NVALS (2*NUM_CLASSES + 1)  // 47
#define SMOOTH 1e-5f
#define TPX 256                    // pixels per stage (HW % 256 == 0)
#define NSTAGES (NPIX/TPX)         // 8192
#define CNT_SHIFT 43
#define FIX_SCALE 16777216.0f      // 2^24
#define INV_FIX   (1.0f/16777216.0f)

// Stage buffer: 23 logit rows (1KB each) + 1 target row (1KB) = 24576 B.
// Two buffers -> 49152 B dynamic smem per block.
#define BUFSZ   24576
#define TGT_ROW 23
#define SM_TOTAL (2*BUFSZ)

__device__ float g_scratch[NVALS * GRID];
__device__ unsigned int g_count;   // zero-init; self-resetting each launch

__device__ __forceinline__ float warp_sum(float v) {
    #pragma unroll
    for (int off = 16; off; off >>= 1)
        v += __shfl_down_sync(0xffffffffu, v, off);
    return v;
}

__device__ __forceinline__ void cp16(uint32_t dst, const void* src) {
    asm volatile("cp.async.cg.shared.global [%0], [%1], 16;" :: "r"(dst), "l"(src));
}
__device__ __forceinline__ void cp_commit() {
    asm volatile("cp.async.commit_group;" ::: "memory");
}
__device__ __forceinline__ void cp_wait1() {
    asm volatile("cp.async.wait_group 1;" ::: "memory");
}

// 24 rows x 1KB = 1536 16B-slots; 256 threads x 6 slots. Flat smem dst
// (g*16); src switches between the 23 strided logit streams and targets.
__device__ __forceinline__ void load_stage(int st, int buf, uint32_t smbase,
                                           const float* __restrict__ pred,
                                           const int*  __restrict__ tgt,
                                           int tid)
{
    const int p0 = st * TPX;
    const int b  = p0 >> HW_SHIFT;
    const int hw = p0 & (HW - 1);
    const float* base = pred + (size_t)b * (NUM_CLASSES * HW) + hw;
    const uint32_t dst0 = smbase + buf * BUFSZ;
    #pragma unroll
    for (int s = 0; s < 6; s++) {
        const int g   = s * BLOCK + tid;
        const int row = g >> 6;          // 0..23
        const int off = (g & 63) << 2;   // float offset within row, 0..252
        const void* src = (row < TGT_ROW)
            ? (const void*)(base + (size_t)row * HW + off)
            : (const void*)(tgt + p0 + off);
        cp16(dst0 + (uint32_t)g * 16u, src);
    }
}

__global__ __launch_bounds__(BLOCK, 3)
void combined_loss_fused(const float* __restrict__ pred,
                         const int*  __restrict__ tgt,
                         float* __restrict__ out)
{
    extern __shared__ char smem_raw[];
    uint32_t smbase;
    asm("{ .reg .u64 t; cvta.to.shared.u64 t, %1; cvt.u32.u64 %0, t; }"
        : "=r"(smbase) : "l"(smem_raw));

    // Per-warp packed accumulators: bits[43:64)=count, bits[0:43)=inter*2^24
    __shared__ unsigned long long s_ic[NWARPS][NUM_CLASSES];
    for (int i = threadIdx.x; i < NWARPS * NUM_CLASSES; i += BLOCK)
        ((unsigned long long*)s_ic)[i] = 0ull;
    __syncthreads();

    float acc_den[NUM_CLASSES];
    #pragma unroll
    for (int c = 0; c < NUM_CLASSES; c++) acc_den[c] = 0.f;
    float acc_ce = 0.f;

    const int tid  = threadIdx.x;
    const int lane = tid & 31;
    const int warp = tid >> 5;
    const int bk   = blockIdx.x;

    // Pipeline prologue (bk+GRID < NSTAGES always)
    load_stage(bk, 0, smbase, pred, tgt, tid);
    cp_commit();
    load_stage(bk + GRID, 1, smbase, pred, tgt, tid);
    cp_commit();

    for (int i = 0; ; i++) {
        const int st = bk + i * GRID;
        if (st >= NSTAGES) break;
        const int buf = i & 1;

        cp_wait1();            // this stage's group complete (in-order)
        __syncthreads();

        const float* sd = (const float*)(smem_raw + buf * BUFSZ);
        const int t = ((const int*)(smem_raw + buf * BUFSZ + TGT_ROW * 1024))[tid];

        // One pixel/thread from smem: 23 LDS.32, constant offsets.
        float x[NUM_CLASSES];
        float m  = -1e30f;
        float xt = 0.f;
        #pragma unroll
        for (int c = 0; c < NUM_CLASSES; c++) {
            x[c] = sd[c * TPX + tid];
            m = fmaxf(m, x[c]);
            xt = (c == t) ? x[c] : xt;
        }

        float s = 0.f;
        #pragma unroll
        for (int c = 0; c < NUM_CLASSES; c++) {
            x[c] = __expf(x[c] - m);
            s += x[c];
        }
        const float inv = 1.0f / s;

        #pragma unroll
        for (int c = 0; c < NUM_CLASSES; c++)
            acc_den[c] = fmaf(x[c], inv, acc_den[c]);

        acc_ce += (m + __logf(s)) - xt;
        const float pt = __expf(xt - m) * inv;
        const unsigned long long u =
            (unsigned long long)(pt * FIX_SCALE) + (1ull << CNT_SHIFT);
        atomicAdd(&s_ic[warp][t], u);

        __syncthreads();       // all reads of buf done before refill

        const int stn = st + 2 * GRID;
        if (stn < NSTAGES)
            load_stage(stn, buf, smbase, pred, tgt, tid);
        cp_commit();           // uniform group count even when empty
    }

    // Deterministic block reduction for den + ce
    __shared__ float s_part[NUM_CLASSES + 1][NWARPS];
    #pragma unroll
    for (int c = 0; c < NUM_CLASSES; c++) {
        float v = warp_sum(acc_den[c]);
        if (lane == 0) s_part[c][warp] = v;
    }
    {
        float v = warp_sum(acc_ce);
        if (lane == 0) s_part[NUM_CLASSES][warp] = v;
    }
    __syncthreads();

    if (threadIdx.x < NUM_CLASSES) {
        const int c = threadIdx.x;
        unsigned long long tot = 0ull;
        float den = 0.f;
        #pragma unroll
        for (int w = 0; w < NWARPS; w++) {
            tot += s_ic[w][c];
            den += s_part[c][w];
        }
        const float inter = (float)(tot & ((1ull << CNT_SHIFT) - 1ull)) * INV_FIX;
        const float cnt   = (float)(tot >> CNT_SHIFT);
        g_scratch[c * GRID + blockIdx.x] = inter;
        g_scratch[(NUM_CLASSES + c) * GRID + blockIdx.x] = den + cnt;
    } else if (threadIdx.x == NUM_CLASSES) {
        float ce = 0.f;
        #pragma unroll
        for (int w = 0; w < NWARPS; w++) ce += s_part[NUM_CLASSES][w];
        g_scratch[2 * NUM_CLASSES * GRID + blockIdx.x] = ce;
    }

    // Last-block final reduction (fixed block-index order -> deterministic)
    __shared__ bool is_last;
    __threadfence();
    if (threadIdx.x == 0) {
        unsigned int v = atomicAdd(&g_count, 1u);
        is_last = (v == GRID - 1);
        if (is_last) g_count = 0u;   // reset for next graph replay
    }
    __syncthreads();
    if (!is_last) return;

    __shared__ float finals[NVALS];
    for (int v = warp; v < NVALS; v += NWARPS) {
        float s = 0.f;
        for (int bki = lane; bki < GRID; bki += 32)
            s += __ldcg(&g_scratch[v * GRID + bki]);
        s = warp_sum(s);
        if (lane == 0) finals[v] = s;
    }
    __syncthreads();

    if (threadIdx.x == 0) {
        float dl = 0.f;
        #pragma unroll
        for (int c = 0; c < NUM_CLASSES; c++) {
            const float inter = finals[c];
            const float den   = finals[NUM_CLASSES + c];
            dl += 1.0f - (2.0f * inter + SMOOTH) / (den + SMOOTH);
        }
        dl *= (1.0f / NUM_CLASSES);
        const float ce = finals[2 * NUM_CLASSES] * (1.0f / (float)NPIX);
        out[0] = 0.5f * dl + 0.5f * ce;
    }
}

extern "C" void kernel_launch(void* const* d_in, const int* in_sizes, int n_in,
                              void* d_out, int out_size)
{
    const float* pred = (const float*)d_in[0];
    const int*   tgt  = (const int*)d_in[1];
    float*       out  = (float*)d_out;
    (void)in_sizes; (void)n_in; (void)out_size;

    cudaFuncSetAttribute(combined_loss_fused,
                         cudaFuncAttributeMaxDynamicSharedMemorySize, SM_TOTAL);
    combined_loss_fused<<<GRID, BLOCK, SM_TOTAL>>>(pred, tgt, out);
}